// round 9
// baseline (speedup 1.0000x reference)
#include <cuda_runtime.h>
#include <cstdint>

#define N_NODES 100000
#define N_EDGES 3200000
#define N_FEAT  24
#define FPAD    32                 // padded feature stride (128 bytes)
#define LAYERS  6
#define EDGE_CAP 4000000           // padded total <= E + 7N = 3.9M; +tail zero block
#define ZPAD (EDGE_CAP - 4)        // 4 permanent-zero edges for short-row redirect
#define BUILD_BLOCKS  148
#define BUILD_THREADS 1024
#define CHUNK 676                  // ceil(N_NODES / BUILD_BLOCKS)

// ---------------------------------------------------------------------------
// Scratch (allocation-free rule: __device__ globals).
// Padded CSR: each row's g_edge segment is padded to a multiple of 8. Pad
// slots (and the ZPAD block) are NEVER written; __device__ globals are
// zero-init, so they are permanently (val=0, off=0) -> harmless gathers of
// src[lane] scaled by 0. Deterministic layout -> replay-safe.
// Feature buffers padded to FPAD=32 floats (128B): 1-line gathers.
// ---------------------------------------------------------------------------
__device__ __align__(16) float  g_bufP[(size_t)N_NODES * FPAD];
__device__ __align__(16) float  g_bufQ[(size_t)N_NODES * FPAD];
__device__ __align__(16) float2 g_edge[EDGE_CAP];   // (val, col*128 bits)
__device__ int g_cnt[N_NODES];        // real row lengths (build only)
__device__ int g_rowptr[N_NODES + 1]; // PADDED exclusive prefix
__device__ int g_cursor[N_NODES];
__device__ int g_bsum[BUILD_BLOCKS];
__device__ int g_boff[BUILD_BLOCKS];
// Monotone: int32 inputs -> set to 1 every run (idempotent); int64 -> stays 0.
__device__ int g_flag = 0;
// Monotone ticket barrier counter; never reset -> replay-safe.
__device__ unsigned g_bar = 0;

// ---------------------------------------------------------------------------
// Software grid barrier (persistent build kernel; 148 blocks = wave 1).
// ---------------------------------------------------------------------------
__device__ __forceinline__ void grid_barrier() {
    __syncthreads();
    if (threadIdx.x == 0) {
        __threadfence();
        unsigned ticket = atomicAdd(&g_bar, 1u);
        unsigned target = (ticket / BUILD_BLOCKS + 1u) * BUILD_BLOCKS;
        unsigned v;
        do {
            asm volatile("ld.global.acquire.gpu.u32 %0, [%1];"
                         : "=r"(v) : "l"(&g_bar));
            if (v < target) __nanosleep(64);
        } while (v < target);
    }
    __syncthreads();
}

__device__ __forceinline__ int load_idx(const void* p, int e, int flag) {
    int v = (flag == 1) ? ((const int*)p)[e] : (int)((const long long*)p)[e];
    return min(max(v, 0), N_NODES - 1);   // fault guard
}

// ---------------------------------------------------------------------------
// Persistent single-launch CSR build + x copy-in:
//   phase 0: zero counts, dtype probe (JAX x64-off downcasts int64->int32;
//            odd int32 words all-zero iff buffer is int64), copy x -> bufP
//   phase 1: row histogram
//   phase 2: exclusive scan of PADDED counts -> g_rowptr, g_cursor
//   phase 3: scatter (val, col*128) into row-sorted padded g_edge
// ---------------------------------------------------------------------------
__global__ void __launch_bounds__(BUILD_THREADS)
build_csr_kernel(const void* __restrict__ rptr,
                 const void* __restrict__ cptr,
                 const float* __restrict__ vals,
                 const float* __restrict__ x) {
    const int tid    = threadIdx.x;
    const int gid    = blockIdx.x * BUILD_THREADS + tid;
    const int stride = BUILD_BLOCKS * BUILD_THREADS;

    // --- phase 0 ---
    for (int i = gid; i < N_NODES; i += stride) g_cnt[i] = 0;
    const int* p32 = (const int*)rptr;
    for (int i = gid; i < N_EDGES / 2; i += stride)
        if (p32[2 * i + 1] != 0) g_flag = 1;
    for (int i = gid; i < N_NODES * N_FEAT; i += stride) {
        int r = i / N_FEAT, f = i - r * N_FEAT;
        g_bufP[r * FPAD + f] = x[i];
    }
    grid_barrier();

    const int flag = g_flag;

    // --- phase 1: histogram ---
    for (int e = gid; e < N_EDGES; e += stride)
        atomicAdd(&g_cnt[load_idx(rptr, e, flag)], 1);
    grid_barrier();

    // --- phase 2a: block-local exclusive scan of padded counts ---
    {
        __shared__ int s_w[32];
        int lane = tid & 31, wid = tid >> 5;
        int i = blockIdx.x * CHUNK + tid;
        int v = (tid < CHUNK && i < N_NODES) ? ((g_cnt[i] + 7) & ~7) : 0;
        int s = v;
        #pragma unroll
        for (int off = 1; off < 32; off <<= 1) {
            int n = __shfl_up_sync(0xffffffffu, s, off);
            if (lane >= off) s += n;
        }
        if (lane == 31) s_w[wid] = s;
        __syncthreads();
        if (wid == 0) {
            int ws = s_w[lane];
            #pragma unroll
            for (int off = 1; off < 32; off <<= 1) {
                int n = __shfl_up_sync(0xffffffffu, ws, off);
                if (lane >= off) ws += n;
            }
            s_w[lane] = ws;
        }
        __syncthreads();
        int woff = (wid > 0) ? s_w[wid - 1] : 0;
        if (tid < CHUNK && i < N_NODES) g_rowptr[i] = woff + s - v;
        if (tid == BUILD_THREADS - 1) g_bsum[blockIdx.x] = s_w[31];
    }
    grid_barrier();

    // --- phase 2b: block 0 scans the 148 block sums ---
    {
        __shared__ int sb[BUILD_BLOCKS];
        if (blockIdx.x == 0) {
            if (tid < BUILD_BLOCKS) sb[tid] = g_bsum[tid];
            __syncthreads();
            for (int off = 1; off < BUILD_BLOCKS; off <<= 1) {
                int t = (tid < BUILD_BLOCKS && tid >= off) ? sb[tid - off] : 0;
                __syncthreads();
                if (tid < BUILD_BLOCKS) sb[tid] += t;
                __syncthreads();
            }
            if (tid < BUILD_BLOCKS) g_boff[tid] = sb[tid] - g_bsum[tid];
            if (tid == BUILD_BLOCKS - 1) g_rowptr[N_NODES] = sb[BUILD_BLOCKS - 1];
        }
    }
    grid_barrier();

    // --- phase 2c: add block offsets; init cursors ---
    for (int i = gid; i < N_NODES; i += stride) {
        int r = g_rowptr[i] + g_boff[i / CHUNK];
        g_rowptr[i] = r;
        g_cursor[i] = r;
    }
    grid_barrier();

    // --- phase 3: place edges (payload: val, col*128 byte offset) ---
    for (int e = gid; e < N_EDGES; e += stride) {
        int r = load_idx(rptr, e, flag);
        int c = load_idx(cptr, e, flag);
        int pos = atomicAdd(&g_cursor[r], 1);
        g_edge[pos] = make_float2(vals[e], __int_as_float(c * (FPAD * 4)));
    }
}

// ---------------------------------------------------------------------------
// CSR SpMM: one warp per TWO adjacent rows, interleaved. Lane f owns
// feature f (24 active). Per iteration: 4 edges from EACH row (2x LDG.128
// edge loads + 4 gathers + 4 FFMAs per row) -> 8 independent gathers in
// flight per warp, two independent FMA chains, and warp lifetime doubled so
// startup latency amortizes. The shorter row's exhausted iterations are
// redirected to the permanent-zero ZPAD block (1 compare+select per row per
// iteration, no per-edge masking). Padded rowptr deltas give exact
// ceil(len/8)*8 batch counts. No atomics; each output written exactly once.
// ---------------------------------------------------------------------------
__global__ void __launch_bounds__(256)
spmm_csr_kernel(const float* __restrict__ src, float* __restrict__ dst,
                int dst_stride) {
    int w    = (blockIdx.x * blockDim.x + threadIdx.x) >> 5;  // row pair
    int lane = threadIdx.x & 31;

    int rA = 2 * w;
    int sA = g_rowptr[rA];
    int sB = g_rowptr[rA + 1];
    int sE = g_rowptr[rA + 2];
    int nA = sB - sA;                 // multiples of 8
    int nB = sE - sB;
    int iters = max(nA, nB) >> 2;     // 4 edges per row per iteration

    const char* sp = (const char*)src + lane * 4;

    float a0 = 0.f, a1 = 0.f, a2 = 0.f, a3 = 0.f;
    float b0 = 0.f, b1 = 0.f, b2 = 0.f, b3 = 0.f;

    for (int i = 0; i < iters; i++) {
        int o  = i * 4;
        int eA = (o < nA) ? (sA + o) : ZPAD;
        int eB = (o < nB) ? (sB + o) : ZPAD;

        float4 pA0 = *(const float4*)&g_edge[eA];
        float4 pA1 = *(const float4*)&g_edge[eA + 2];
        float4 pB0 = *(const float4*)&g_edge[eB];
        float4 pB1 = *(const float4*)&g_edge[eB + 2];

        a0 = fmaf(pA0.x, *(const float*)(sp + __float_as_int(pA0.y)), a0);
        a1 = fmaf(pA0.z, *(const float*)(sp + __float_as_int(pA0.w)), a1);
        a2 = fmaf(pA1.x, *(const float*)(sp + __float_as_int(pA1.y)), a2);
        a3 = fmaf(pA1.z, *(const float*)(sp + __float_as_int(pA1.w)), a3);
        b0 = fmaf(pB0.x, *(const float*)(sp + __float_as_int(pB0.y)), b0);
        b1 = fmaf(pB0.z, *(const float*)(sp + __float_as_int(pB0.w)), b1);
        b2 = fmaf(pB1.x, *(const float*)(sp + __float_as_int(pB1.y)), b2);
        b3 = fmaf(pB1.z, *(const float*)(sp + __float_as_int(pB1.w)), b3);
    }

    float accA = (a0 + a1) + (a2 + a3);
    float accB = (b0 + b1) + (b2 + b3);
    if (lane < N_FEAT) {
        dst[(size_t)rA * dst_stride + lane]       = accA;
        dst[(size_t)(rA + 1) * dst_stride + lane] = accB;
    }
}

// ---------------------------------------------------------------------------
// kernel_launch: one build launch, then 6 SpMMs. x copied into padded bufP
// inside build; chain P->Q->P->Q->P->Q->out (final write at stride 24).
// Default stream, no syncs, no allocations -> graph-capturable.
// ---------------------------------------------------------------------------
extern "C" void kernel_launch(void* const* d_in, const int* in_sizes, int n_in,
                              void* d_out, int out_size) {
    const float* x    = (const float*)d_in[0];  // [N_NODES, N_FEAT]
    const float* vals = (const float*)d_in[1];  // [N_EDGES]
    const void*  rraw = d_in[2];                // [N_EDGES] int32 or int64
    const void*  craw = d_in[3];                // [N_EDGES] int32 or int64
    float* out = (float*)d_out;                 // [N_NODES, N_FEAT]

    float* bufP;
    float* bufQ;
    cudaGetSymbolAddress((void**)&bufP, g_bufP);
    cudaGetSymbolAddress((void**)&bufQ, g_bufQ);

    const int sblocks = N_NODES / 16;   // 6250 blocks; warp per row pair

    build_csr_kernel<<<BUILD_BLOCKS, BUILD_THREADS>>>(rraw, craw, vals, x);

    // 6 layers: P -> Q -> P -> Q -> P -> Q -> out
    const float* srcs[LAYERS] = { bufP, bufQ, bufP, bufQ, bufP, bufQ };
    float*       dsts[LAYERS] = { bufQ, bufP, bufQ, bufP, bufQ, out };
    int          dstr[LAYERS] = { FPAD, FPAD, FPAD, FPAD, FPAD, N_FEAT };

    for (int l = 0; l < LAYERS; l++) {
        spmm_csr_kernel<<<sblocks, 256>>>(srcs[l], dsts[l], dstr[l]);
    }
}

// round 10
// speedup vs baseline: 1.2406x; 1.2406x over previous
#include <cuda_runtime.h>
#include <cstdint>

#define N_NODES 100000
#define N_EDGES 3200000
#define N_FEAT  24
#define FPAD    32                 // padded feature stride (128 bytes)
#define LAYERS  6
#define EDGE_CAP 4000000           // padded total <= E + 7N = 3.9M
#define BUILD_BLOCKS  148
#define BUILD_THREADS 1024
#define CHUNK 676                  // ceil(N_NODES / BUILD_BLOCKS)

// ---------------------------------------------------------------------------
// Scratch (allocation-free rule: __device__ globals).
// Padded CSR: each row's g_edge segment is padded to a multiple of 8. Pad
// slots are NEVER written; __device__ globals are zero-init, so pads are
// permanently (val=0, off=0) -> harmless gathers of src[lane] scaled by 0.
// Deterministic layout -> replay-safe. Feature buffers padded to FPAD=32
// floats (128B): every gather lands in exactly one L1/L2 line.
// ---------------------------------------------------------------------------
__device__ __align__(16) float  g_bufP[(size_t)N_NODES * FPAD];
__device__ __align__(16) float  g_bufQ[(size_t)N_NODES * FPAD];
__device__ __align__(16) float2 g_edge[EDGE_CAP];   // (val, col*128 bits)
__device__ int g_cnt[N_NODES];        // real row lengths (build only)
__device__ int g_rowptr[N_NODES + 1]; // PADDED exclusive prefix
__device__ int g_cursor[N_NODES];
__device__ int g_bsum[BUILD_BLOCKS];
__device__ int g_boff[BUILD_BLOCKS];
// Monotone: int32 inputs -> set to 1 every run (idempotent); int64 -> stays 0.
__device__ int g_flag = 0;
// Monotone ticket barrier counter; never reset -> replay-safe.
__device__ unsigned g_bar = 0;

// ---------------------------------------------------------------------------
// Software grid barrier (persistent build kernel; 148 blocks = wave 1).
// ---------------------------------------------------------------------------
__device__ __forceinline__ void grid_barrier() {
    __syncthreads();
    if (threadIdx.x == 0) {
        __threadfence();
        unsigned ticket = atomicAdd(&g_bar, 1u);
        unsigned target = (ticket / BUILD_BLOCKS + 1u) * BUILD_BLOCKS;
        unsigned v;
        do {
            asm volatile("ld.global.acquire.gpu.u32 %0, [%1];"
                         : "=r"(v) : "l"(&g_bar));
            if (v < target) __nanosleep(64);
        } while (v < target);
    }
    __syncthreads();
}

__device__ __forceinline__ int load_idx(const void* p, int e, int flag) {
    int v = (flag == 1) ? ((const int*)p)[e] : (int)((const long long*)p)[e];
    return min(max(v, 0), N_NODES - 1);   // fault guard
}

// ---------------------------------------------------------------------------
// Persistent single-launch CSR build + x copy-in:
//   phase 0: zero counts, dtype probe (JAX x64-off downcasts int64->int32;
//            odd int32 words all-zero iff buffer is int64), copy x -> bufP
//   phase 1: row histogram
//   phase 2: exclusive scan of PADDED counts -> g_rowptr, g_cursor
//   phase 3: scatter (val, col*128) into row-sorted padded g_edge
// ---------------------------------------------------------------------------
__global__ void __launch_bounds__(BUILD_THREADS)
build_csr_kernel(const void* __restrict__ rptr,
                 const void* __restrict__ cptr,
                 const float* __restrict__ vals,
                 const float* __restrict__ x) {
    const int tid    = threadIdx.x;
    const int gid    = blockIdx.x * BUILD_THREADS + tid;
    const int stride = BUILD_BLOCKS * BUILD_THREADS;

    // --- phase 0 ---
    for (int i = gid; i < N_NODES; i += stride) g_cnt[i] = 0;
    const int* p32 = (const int*)rptr;
    for (int i = gid; i < N_EDGES / 2; i += stride)
        if (p32[2 * i + 1] != 0) g_flag = 1;
    for (int i = gid; i < N_NODES * N_FEAT; i += stride) {
        int r = i / N_FEAT, f = i - r * N_FEAT;
        g_bufP[r * FPAD + f] = x[i];
    }
    grid_barrier();

    const int flag = g_flag;

    // --- phase 1: histogram ---
    for (int e = gid; e < N_EDGES; e += stride)
        atomicAdd(&g_cnt[load_idx(rptr, e, flag)], 1);
    grid_barrier();

    // --- phase 2a: block-local exclusive scan of padded counts ---
    {
        __shared__ int s_w[32];
        int lane = tid & 31, wid = tid >> 5;
        int i = blockIdx.x * CHUNK + tid;
        int v = (tid < CHUNK && i < N_NODES) ? ((g_cnt[i] + 7) & ~7) : 0;
        int s = v;
        #pragma unroll
        for (int off = 1; off < 32; off <<= 1) {
            int n = __shfl_up_sync(0xffffffffu, s, off);
            if (lane >= off) s += n;
        }
        if (lane == 31) s_w[wid] = s;
        __syncthreads();
        if (wid == 0) {
            int ws = s_w[lane];
            #pragma unroll
            for (int off = 1; off < 32; off <<= 1) {
                int n = __shfl_up_sync(0xffffffffu, ws, off);
                if (lane >= off) ws += n;
            }
            s_w[lane] = ws;
        }
        __syncthreads();
        int woff = (wid > 0) ? s_w[wid - 1] : 0;
        if (tid < CHUNK && i < N_NODES) g_rowptr[i] = woff + s - v;
        if (tid == BUILD_THREADS - 1) g_bsum[blockIdx.x] = s_w[31];
    }
    grid_barrier();

    // --- phase 2b: block 0 scans the 148 block sums ---
    {
        __shared__ int sb[BUILD_BLOCKS];
        if (blockIdx.x == 0) {
            if (tid < BUILD_BLOCKS) sb[tid] = g_bsum[tid];
            __syncthreads();
            for (int off = 1; off < BUILD_BLOCKS; off <<= 1) {
                int t = (tid < BUILD_BLOCKS && tid >= off) ? sb[tid - off] : 0;
                __syncthreads();
                if (tid < BUILD_BLOCKS) sb[tid] += t;
                __syncthreads();
            }
            if (tid < BUILD_BLOCKS) g_boff[tid] = sb[tid] - g_bsum[tid];
            if (tid == BUILD_BLOCKS - 1) g_rowptr[N_NODES] = sb[BUILD_BLOCKS - 1];
        }
    }
    grid_barrier();

    // --- phase 2c: add block offsets; init cursors ---
    for (int i = gid; i < N_NODES; i += stride) {
        int r = g_rowptr[i] + g_boff[i / CHUNK];
        g_rowptr[i] = r;
        g_cursor[i] = r;
    }
    grid_barrier();

    // --- phase 3: place edges (payload: val, col*128 byte offset) ---
    for (int e = gid; e < N_EDGES; e += stride) {
        int r = load_idx(rptr, e, flag);
        int c = load_idx(cptr, e, flag);
        int pos = atomicAdd(&g_cursor[r], 1);
        g_edge[pos] = make_float2(vals[e], __int_as_float(c * (FPAD * 4)));
    }
}

// ---------------------------------------------------------------------------
// CSR SpMM: one warp per row, lane f owns feature f (24 active; lanes 24-31
// read permanent-zero pad columns and never write). No masking, no
// remainder, no g_cnt load: the loop runs start..padded_end in full
// float4-aligned 8-edge batches; pad entries are permanent zeros.
// DSTRIDE is a template constant (FPAD for intermediate layers, N_FEAT for
// the final d_out write) to keep register count down.
// __launch_bounds__(256, 8) pins regs <= 32 -> 8 resident blocks/SM = 100%
// theoretical occupancy (the R8/R9 regressions were 34/44-reg occupancy
// cliffs: 7 and 5 blocks/SM).
// ---------------------------------------------------------------------------
template <int DSTRIDE>
__global__ void __launch_bounds__(256, 8)
spmm_csr_kernel(const float* __restrict__ src, float* __restrict__ dst) {
    int w    = (blockIdx.x * blockDim.x + threadIdx.x) >> 5;  // row
    int lane = threadIdx.x & 31;

    int start = g_rowptr[w];          // multiple of 8
    int end   = g_rowptr[w + 1];      // padded end (pads contribute zero)
    const char* sp = (const char*)src + lane * 4;

    float a0 = 0.f, a1 = 0.f, a2 = 0.f, a3 = 0.f;
    float a4 = 0.f, a5 = 0.f, a6 = 0.f, a7 = 0.f;

    for (int e = start; e < end; e += 8) {
        float4 p0 = *(const float4*)&g_edge[e + 0];
        float4 p1 = *(const float4*)&g_edge[e + 2];
        float4 p2 = *(const float4*)&g_edge[e + 4];
        float4 p3 = *(const float4*)&g_edge[e + 6];
        a0 = fmaf(p0.x, *(const float*)(sp + __float_as_int(p0.y)), a0);
        a1 = fmaf(p0.z, *(const float*)(sp + __float_as_int(p0.w)), a1);
        a2 = fmaf(p1.x, *(const float*)(sp + __float_as_int(p1.y)), a2);
        a3 = fmaf(p1.z, *(const float*)(sp + __float_as_int(p1.w)), a3);
        a4 = fmaf(p2.x, *(const float*)(sp + __float_as_int(p2.y)), a4);
        a5 = fmaf(p2.z, *(const float*)(sp + __float_as_int(p2.w)), a5);
        a6 = fmaf(p3.x, *(const float*)(sp + __float_as_int(p3.y)), a6);
        a7 = fmaf(p3.z, *(const float*)(sp + __float_as_int(p3.w)), a7);
    }

    float acc = ((a0 + a1) + (a2 + a3)) + ((a4 + a5) + (a6 + a7));
    if (lane < N_FEAT) dst[(size_t)w * DSTRIDE + lane] = acc;
}

// ---------------------------------------------------------------------------
// kernel_launch: one build launch, then 6 SpMMs. x copied into padded bufP
// inside build; chain P->Q->P->Q->P->Q->out (final instantiation writes at
// stride 24). Default stream, no syncs, no allocations -> graph-capturable.
// ---------------------------------------------------------------------------
extern "C" void kernel_launch(void* const* d_in, const int* in_sizes, int n_in,
                              void* d_out, int out_size) {
    const float* x    = (const float*)d_in[0];  // [N_NODES, N_FEAT]
    const float* vals = (const float*)d_in[1];  // [N_EDGES]
    const void*  rraw = d_in[2];                // [N_EDGES] int32 or int64
    const void*  craw = d_in[3];                // [N_EDGES] int32 or int64
    float* out = (float*)d_out;                 // [N_NODES, N_FEAT]

    float* bufP;
    float* bufQ;
    cudaGetSymbolAddress((void**)&bufP, g_bufP);
    cudaGetSymbolAddress((void**)&bufQ, g_bufQ);

    const int sblocks = N_NODES / 8;   // 12500 blocks, warp per row

    build_csr_kernel<<<BUILD_BLOCKS, BUILD_THREADS>>>(rraw, craw, vals, x);

    // Layers 1-5 into padded buffers, final layer into d_out (stride 24).
    spmm_csr_kernel<FPAD><<<sblocks, 256>>>(bufP, bufQ);
    spmm_csr_kernel<FPAD><<<sblocks, 256>>>(bufQ, bufP);
    spmm_csr_kernel<FPAD><<<sblocks, 256>>>(bufP, bufQ);
    spmm_csr_kernel<FPAD><<<sblocks, 256>>>(bufQ, bufP);
    spmm_csr_kernel<FPAD><<<sblocks, 256>>>(bufP, bufQ);
    spmm_csr_kernel<N_FEAT><<<sblocks, 256>>>(bufQ, out);
}

// round 11
// speedup vs baseline: 1.4171x; 1.1423x over previous
#include <cuda_runtime.h>
#include <cstdint>

#define N_NODES 100000
#define N_EDGES 3200000
#define N_FEAT  24
#define FPAD    32                 // padded feature stride (128 bytes)
#define LAYERS  6
#define EDGE_CAP 4000000           // padded total <= E + 3N = 3.5M
#define BUILD_BLOCKS  148
#define BUILD_THREADS 1024
#define CHUNK 676                  // ceil(N_NODES / BUILD_BLOCKS)

// ---------------------------------------------------------------------------
// Scratch (allocation-free rule: __device__ globals).
// Padded CSR: each row's g_edge segment is padded to a multiple of 4. Pad
// slots are NEVER written; __device__ globals are zero-init, so pads are
// permanently (val=0, off=0) -> harmless gathers of row 0 scaled by 0.
// Deterministic layout -> replay-safe. Feature buffers padded to FPAD=32
// floats (128B): a 4-group float4 gather spans exactly 4 aligned rows.
// ---------------------------------------------------------------------------
__device__ __align__(16) float  g_bufP[(size_t)N_NODES * FPAD];
__device__ __align__(16) float  g_bufQ[(size_t)N_NODES * FPAD];
__device__ __align__(16) float2 g_edge[EDGE_CAP];   // (val, col*128 bits)
__device__ int g_cnt[N_NODES];        // real row lengths (build only)
__device__ int g_rowptr[N_NODES + 1]; // PADDED exclusive prefix
__device__ int g_cursor[N_NODES];
__device__ int g_bsum[BUILD_BLOCKS];
__device__ int g_boff[BUILD_BLOCKS];
// Monotone: int32 inputs -> set to 1 every run (idempotent); int64 -> stays 0.
__device__ int g_flag = 0;
// Monotone ticket barrier counter; never reset -> replay-safe.
__device__ unsigned g_bar = 0;

// ---------------------------------------------------------------------------
// Software grid barrier (persistent build kernel; 148 blocks = wave 1).
// ---------------------------------------------------------------------------
__device__ __forceinline__ void grid_barrier() {
    __syncthreads();
    if (threadIdx.x == 0) {
        __threadfence();
        unsigned ticket = atomicAdd(&g_bar, 1u);
        unsigned target = (ticket / BUILD_BLOCKS + 1u) * BUILD_BLOCKS;
        unsigned v;
        do {
            asm volatile("ld.global.acquire.gpu.u32 %0, [%1];"
                         : "=r"(v) : "l"(&g_bar));
            if (v < target) __nanosleep(64);
        } while (v < target);
    }
    __syncthreads();
}

__device__ __forceinline__ int load_idx(const void* p, int e, int flag) {
    int v = (flag == 1) ? ((const int*)p)[e] : (int)((const long long*)p)[e];
    return min(max(v, 0), N_NODES - 1);   // fault guard
}

// ---------------------------------------------------------------------------
// Persistent single-launch CSR build + x copy-in:
//   phase 0: zero counts, dtype probe (JAX x64-off downcasts int64->int32;
//            odd int32 words all-zero iff buffer is int64), copy x -> bufP
//   phase 1: row histogram
//   phase 2: exclusive scan of counts padded to multiples of 4
//   phase 3: scatter (val, col*128) into row-sorted padded g_edge
// ---------------------------------------------------------------------------
__global__ void __launch_bounds__(BUILD_THREADS)
build_csr_kernel(const void* __restrict__ rptr,
                 const void* __restrict__ cptr,
                 const float* __restrict__ vals,
                 const float* __restrict__ x) {
    const int tid    = threadIdx.x;
    const int gid    = blockIdx.x * BUILD_THREADS + tid;
    const int stride = BUILD_BLOCKS * BUILD_THREADS;

    // --- phase 0 ---
    for (int i = gid; i < N_NODES; i += stride) g_cnt[i] = 0;
    const int* p32 = (const int*)rptr;
    for (int i = gid; i < N_EDGES / 2; i += stride)
        if (p32[2 * i + 1] != 0) g_flag = 1;
    for (int i = gid; i < N_NODES * N_FEAT; i += stride) {
        int r = i / N_FEAT, f = i - r * N_FEAT;
        g_bufP[r * FPAD + f] = x[i];
    }
    grid_barrier();

    const int flag = g_flag;

    // --- phase 1: histogram ---
    for (int e = gid; e < N_EDGES; e += stride)
        atomicAdd(&g_cnt[load_idx(rptr, e, flag)], 1);
    grid_barrier();

    // --- phase 2a: block-local exclusive scan of padded counts ---
    {
        __shared__ int s_w[32];
        int lane = tid & 31, wid = tid >> 5;
        int i = blockIdx.x * CHUNK + tid;
        int v = (tid < CHUNK && i < N_NODES) ? ((g_cnt[i] + 3) & ~3) : 0;
        int s = v;
        #pragma unroll
        for (int off = 1; off < 32; off <<= 1) {
            int n = __shfl_up_sync(0xffffffffu, s, off);
            if (lane >= off) s += n;
        }
        if (lane == 31) s_w[wid] = s;
        __syncthreads();
        if (wid == 0) {
            int ws = s_w[lane];
            #pragma unroll
            for (int off = 1; off < 32; off <<= 1) {
                int n = __shfl_up_sync(0xffffffffu, ws, off);
                if (lane >= off) ws += n;
            }
            s_w[lane] = ws;
        }
        __syncthreads();
        int woff = (wid > 0) ? s_w[wid - 1] : 0;
        if (tid < CHUNK && i < N_NODES) g_rowptr[i] = woff + s - v;
        if (tid == BUILD_THREADS - 1) g_bsum[blockIdx.x] = s_w[31];
    }
    grid_barrier();

    // --- phase 2b: block 0 scans the 148 block sums ---
    {
        __shared__ int sb[BUILD_BLOCKS];
        if (blockIdx.x == 0) {
            if (tid < BUILD_BLOCKS) sb[tid] = g_bsum[tid];
            __syncthreads();
            for (int off = 1; off < BUILD_BLOCKS; off <<= 1) {
                int t = (tid < BUILD_BLOCKS && tid >= off) ? sb[tid - off] : 0;
                __syncthreads();
                if (tid < BUILD_BLOCKS) sb[tid] += t;
                __syncthreads();
            }
            if (tid < BUILD_BLOCKS) g_boff[tid] = sb[tid] - g_bsum[tid];
            if (tid == BUILD_BLOCKS - 1) g_rowptr[N_NODES] = sb[BUILD_BLOCKS - 1];
        }
    }
    grid_barrier();

    // --- phase 2c: add block offsets; init cursors ---
    for (int i = gid; i < N_NODES; i += stride) {
        int r = g_rowptr[i] + g_boff[i / CHUNK];
        g_rowptr[i] = r;
        g_cursor[i] = r;
    }
    grid_barrier();

    // --- phase 3: place edges (payload: val, col*128 byte offset) ---
    for (int e = gid; e < N_EDGES; e += stride) {
        int r = load_idx(rptr, e, flag);
        int c = load_idx(cptr, e, flag);
        int pos = atomicAdd(&g_cursor[r], 1);
        g_edge[pos] = make_float2(vals[e], __int_as_float(c * (FPAD * 4)));
    }
}

// ---------------------------------------------------------------------------
// CSR SpMM, 4-edges-per-gather-instruction. One warp per row. Lanes split
// into 4 groups of 8 (g = lane>>3, q = lane&7); per iteration the warp
// consumes 4 edges:
//   2x uniform LDG.128 edge loads (E01 = v0,o0,v1,o1; E23 = v2,o2,v3,o3)
//   1x LDG.128 gather: group g reads edge g's ENTIRE 128B feature row
//     (lane addr = src + off_g + q*16) -> 3 LDG per 4 edges (was 6).
//   group-select of (v,off) via 2 hoisted predicates -> SELs, then 4 FFMA
//   into a per-lane float4 accumulator (feats 4q..4q+3 of edge-stream g).
// Epilogue: butterfly (xor 8, xor 16) folds the 4 groups; lanes 0-5 write
// one float4 each (24 floats; 96B is 16B-aligned even at stride 24).
// Pads are permanent zeros -> no masking. LSU-rate bound says this is the
// win: rt_LDG = 1.82 cyc/instr regardless of width.
// ---------------------------------------------------------------------------
template <int DSTRIDE>
__global__ void __launch_bounds__(256, 8)
spmm_csr_kernel(const float* __restrict__ src, float* __restrict__ dst) {
    int w    = (blockIdx.x * blockDim.x + threadIdx.x) >> 5;  // row
    int lane = threadIdx.x & 31;

    int start = g_rowptr[w];          // multiple of 4
    int end   = g_rowptr[w + 1];      // padded end (pads contribute zero)

    bool gLo = (lane & 8)  == 0;      // group bit 0 (edge 0/2 vs 1/3)
    bool gHi = (lane & 16) == 0;      // group bit 1 (edges 0,1 vs 2,3)
    const char* sp = (const char*)src + (lane & 7) * 16;

    float4 acc = make_float4(0.f, 0.f, 0.f, 0.f);

    for (int e = start; e < end; e += 4) {
        float4 E01 = *(const float4*)&g_edge[e];       // v0,o0,v1,o1
        float4 E23 = *(const float4*)&g_edge[e + 2];   // v2,o2,v3,o3
        float vv = gHi ? (gLo ? E01.x : E01.z) : (gLo ? E23.x : E23.z);
        float of = gHi ? (gLo ? E01.y : E01.w) : (gLo ? E23.y : E23.w);
        float4 gv = *(const float4*)(sp + __float_as_int(of));
        acc.x = fmaf(vv, gv.x, acc.x);
        acc.y = fmaf(vv, gv.y, acc.y);
        acc.z = fmaf(vv, gv.z, acc.z);
        acc.w = fmaf(vv, gv.w, acc.w);
    }

    // Fold the 4 edge-stream groups: lanes {q, q+8, q+16, q+24} -> lane q.
    acc.x += __shfl_xor_sync(0xffffffffu, acc.x, 8);
    acc.y += __shfl_xor_sync(0xffffffffu, acc.y, 8);
    acc.z += __shfl_xor_sync(0xffffffffu, acc.z, 8);
    acc.w += __shfl_xor_sync(0xffffffffu, acc.w, 8);
    acc.x += __shfl_xor_sync(0xffffffffu, acc.x, 16);
    acc.y += __shfl_xor_sync(0xffffffffu, acc.y, 16);
    acc.z += __shfl_xor_sync(0xffffffffu, acc.z, 16);
    acc.w += __shfl_xor_sync(0xffffffffu, acc.w, 16);

    if (lane < 6)   // lanes 0-5 cover feats 0..23 (float4 each)
        *(float4*)(dst + (size_t)w * DSTRIDE + lane * 4) = acc;
}

// ---------------------------------------------------------------------------
// kernel_launch: one build launch, then 6 SpMMs. x copied into padded bufP
// inside build; chain P->Q->P->Q->P->Q->out (final instantiation writes at
// stride 24). Default stream, no syncs, no allocations -> graph-capturable.
// ---------------------------------------------------------------------------
extern "C" void kernel_launch(void* const* d_in, const int* in_sizes, int n_in,
                              void* d_out, int out_size) {
    const float* x    = (const float*)d_in[0];  // [N_NODES, N_FEAT]
    const float* vals = (const float*)d_in[1];  // [N_EDGES]
    const void*  rraw = d_in[2];                // [N_EDGES] int32 or int64
    const void*  craw = d_in[3];                // [N_EDGES] int32 or int64
    float* out = (float*)d_out;                 // [N_NODES, N_FEAT]

    float* bufP;
    float* bufQ;
    cudaGetSymbolAddress((void**)&bufP, g_bufP);
    cudaGetSymbolAddress((void**)&bufQ, g_bufQ);

    const int sblocks = N_NODES / 8;   // 12500 blocks, warp per row

    build_csr_kernel<<<BUILD_BLOCKS, BUILD_THREADS>>>(rraw, craw, vals, x);

    // Layers 1-5 into padded buffers, final layer into d_out (stride 24).
    spmm_csr_kernel<FPAD><<<sblocks, 256>>>(bufP, bufQ);
    spmm_csr_kernel<FPAD><<<sblocks, 256>>>(bufQ, bufP);
    spmm_csr_kernel<FPAD><<<sblocks, 256>>>(bufP, bufQ);
    spmm_csr_kernel<FPAD><<<sblocks, 256>>>(bufQ, bufP);
    spmm_csr_kernel<FPAD><<<sblocks, 256>>>(bufP, bufQ);
    spmm_csr_kernel<N_FEAT><<<sblocks, 256>>>(bufQ, out);
}

// round 12
// speedup vs baseline: 1.6703x; 1.1787x over previous
#include <cuda_runtime.h>
#include <cstdint>

#define N_NODES 100000
#define N_EDGES 3200000
#define N_FEAT  24
#define FPAD    32                 // padded feature stride (128 bytes)
#define LAYERS  6
#define EDGE_CAP 4000000           // padded total <= E + 7N = 3.9M
#define BUILD_BLOCKS  148
#define BUILD_THREADS 1024
#define CHUNK 676                  // ceil(N_NODES / BUILD_BLOCKS)

// ---------------------------------------------------------------------------
// Scratch (allocation-free rule: __device__ globals).
// Padded CSR: each row's g_edge segment is padded to a multiple of 8. Pad
// slots are NEVER written; __device__ globals are zero-init, so pads are
// permanently (val=0, off=0) -> harmless gathers of row 0 scaled by 0.
// Deterministic layout -> replay-safe. Feature buffers padded to FPAD=32
// floats (128B): a 4-group float4 gather spans exactly 4 aligned rows.
// ---------------------------------------------------------------------------
__device__ __align__(16) float  g_bufP[(size_t)N_NODES * FPAD];
__device__ __align__(16) float  g_bufQ[(size_t)N_NODES * FPAD];
__device__ __align__(16) float2 g_edge[EDGE_CAP];   // (val, col*128 bits)
__device__ int g_cnt[N_NODES];        // real row lengths (build only)
__device__ int g_rowptr[N_NODES + 1]; // PADDED exclusive prefix
__device__ int g_cursor[N_NODES];
__device__ int g_bsum[BUILD_BLOCKS];
__device__ int g_boff[BUILD_BLOCKS];
// Monotone: int32 inputs -> set to 1 every run (idempotent); int64 -> stays 0.
__device__ int g_flag = 0;
// Monotone ticket barrier counter; never reset -> replay-safe.
__device__ unsigned g_bar = 0;

// ---------------------------------------------------------------------------
// Software grid barrier (persistent build kernel; 148 blocks = wave 1).
// ---------------------------------------------------------------------------
__device__ __forceinline__ void grid_barrier() {
    __syncthreads();
    if (threadIdx.x == 0) {
        __threadfence();
        unsigned ticket = atomicAdd(&g_bar, 1u);
        unsigned target = (ticket / BUILD_BLOCKS + 1u) * BUILD_BLOCKS;
        unsigned v;
        do {
            asm volatile("ld.global.acquire.gpu.u32 %0, [%1];"
                         : "=r"(v) : "l"(&g_bar));
            if (v < target) __nanosleep(64);
        } while (v < target);
    }
    __syncthreads();
}

__device__ __forceinline__ int load_idx(const void* p, int e, int flag) {
    int v = (flag == 1) ? ((const int*)p)[e] : (int)((const long long*)p)[e];
    return min(max(v, 0), N_NODES - 1);   // fault guard
}

// ---------------------------------------------------------------------------
// Persistent single-launch CSR build + x copy-in:
//   phase 0: zero counts, dtype probe (JAX x64-off downcasts int64->int32;
//            odd int32 words all-zero iff buffer is int64), copy x -> bufP
//   phase 1: row histogram
//   phase 2: exclusive scan of counts padded to multiples of 8
//   phase 3: scatter (val, col*128) into row-sorted padded g_edge
// ---------------------------------------------------------------------------
__global__ void __launch_bounds__(BUILD_THREADS)
build_csr_kernel(const void* __restrict__ rptr,
                 const void* __restrict__ cptr,
                 const float* __restrict__ vals,
                 const float* __restrict__ x) {
    const int tid    = threadIdx.x;
    const int gid    = blockIdx.x * BUILD_THREADS + tid;
    const int stride = BUILD_BLOCKS * BUILD_THREADS;

    // --- phase 0 ---
    for (int i = gid; i < N_NODES; i += stride) g_cnt[i] = 0;
    const int* p32 = (const int*)rptr;
    for (int i = gid; i < N_EDGES / 2; i += stride)
        if (p32[2 * i + 1] != 0) g_flag = 1;
    for (int i = gid; i < N_NODES * N_FEAT; i += stride) {
        int r = i / N_FEAT, f = i - r * N_FEAT;
        g_bufP[r * FPAD + f] = x[i];
    }
    grid_barrier();

    const int flag = g_flag;

    // --- phase 1: histogram ---
    for (int e = gid; e < N_EDGES; e += stride)
        atomicAdd(&g_cnt[load_idx(rptr, e, flag)], 1);
    grid_barrier();

    // --- phase 2a: block-local exclusive scan of padded counts ---
    {
        __shared__ int s_w[32];
        int lane = tid & 31, wid = tid >> 5;
        int i = blockIdx.x * CHUNK + tid;
        int v = (tid < CHUNK && i < N_NODES) ? ((g_cnt[i] + 7) & ~7) : 0;
        int s = v;
        #pragma unroll
        for (int off = 1; off < 32; off <<= 1) {
            int n = __shfl_up_sync(0xffffffffu, s, off);
            if (lane >= off) s += n;
        }
        if (lane == 31) s_w[wid] = s;
        __syncthreads();
        if (wid == 0) {
            int ws = s_w[lane];
            #pragma unroll
            for (int off = 1; off < 32; off <<= 1) {
                int n = __shfl_up_sync(0xffffffffu, ws, off);
                if (lane >= off) ws += n;
            }
            s_w[lane] = ws;
        }
        __syncthreads();
        int woff = (wid > 0) ? s_w[wid - 1] : 0;
        if (tid < CHUNK && i < N_NODES) g_rowptr[i] = woff + s - v;
        if (tid == BUILD_THREADS - 1) g_bsum[blockIdx.x] = s_w[31];
    }
    grid_barrier();

    // --- phase 2b: block 0 scans the 148 block sums ---
    {
        __shared__ int sb[BUILD_BLOCKS];
        if (blockIdx.x == 0) {
            if (tid < BUILD_BLOCKS) sb[tid] = g_bsum[tid];
            __syncthreads();
            for (int off = 1; off < BUILD_BLOCKS; off <<= 1) {
                int t = (tid < BUILD_BLOCKS && tid >= off) ? sb[tid - off] : 0;
                __syncthreads();
                if (tid < BUILD_BLOCKS) sb[tid] += t;
                __syncthreads();
            }
            if (tid < BUILD_BLOCKS) g_boff[tid] = sb[tid] - g_bsum[tid];
            if (tid == BUILD_BLOCKS - 1) g_rowptr[N_NODES] = sb[BUILD_BLOCKS - 1];
        }
    }
    grid_barrier();

    // --- phase 2c: add block offsets; init cursors ---
    for (int i = gid; i < N_NODES; i += stride) {
        int r = g_rowptr[i] + g_boff[i / CHUNK];
        g_rowptr[i] = r;
        g_cursor[i] = r;
    }
    grid_barrier();

    // --- phase 3: place edges (payload: val, col*128 byte offset) ---
    for (int e = gid; e < N_EDGES; e += stride) {
        int r = load_idx(rptr, e, flag);
        int c = load_idx(cptr, e, flag);
        int pos = atomicAdd(&g_cursor[r], 1);
        g_edge[pos] = make_float2(vals[e], __int_as_float(c * (FPAD * 4)));
    }
}

// ---------------------------------------------------------------------------
// CSR SpMM, per-group edge loads (no selects). One warp per row; lanes split
// into 4 groups of 8 (g = lane>>3, q = lane&7). Per iteration the warp
// consumes 8 edges in two halves; per half:
//   1x LDG.64: group g loads edge (e + g) directly -- the 4 group addresses
//     span 32 aligned bytes = ONE line, one wavefront, zero select ops.
//   1x LDG.128 gather: group g reads its edge's whole 128B feature row
//     (lane addr = src + off_g + q*16; 4 lines, 4 wavefronts).
//   4x FFMA into the per-lane float4 accumulator.
// Two independent halves -> 2 gathers in flight per warp. Rows padded to
// multiples of 8 with permanent-zero entries -> no masking, no remainder.
// Epilogue: butterfly (xor 8, xor 16) folds the 4 groups; lanes 0-5 write
// one float4 each (24 floats; 96B rows stay 16B-aligned at stride 24).
// __launch_bounds__(256, 8) pins regs <= 32 -> 8 blocks/SM (the proven
// occupancy cliff from R8/R9).
// ---------------------------------------------------------------------------
template <int DSTRIDE>
__global__ void __launch_bounds__(256, 8)
spmm_csr_kernel(const float* __restrict__ src, float* __restrict__ dst) {
    int w    = (blockIdx.x * blockDim.x + threadIdx.x) >> 5;  // row
    int lane = threadIdx.x & 31;

    int start = g_rowptr[w];          // multiple of 8
    int end   = g_rowptr[w + 1];      // padded end (pads contribute zero)

    int g = lane >> 3;                // edge-stream group 0..3
    const char* sp = (const char*)src + (lane & 7) * 16;

    float4 acc = make_float4(0.f, 0.f, 0.f, 0.f);

    for (int e = start; e < end; e += 8) {
        float2 e0 = g_edge[e + g];
        float2 e1 = g_edge[e + 4 + g];
        float4 g0 = *(const float4*)(sp + __float_as_int(e0.y));
        float4 g1 = *(const float4*)(sp + __float_as_int(e1.y));
        acc.x = fmaf(e0.x, g0.x, acc.x);
        acc.y = fmaf(e0.x, g0.y, acc.y);
        acc.z = fmaf(e0.x, g0.z, acc.z);
        acc.w = fmaf(e0.x, g0.w, acc.w);
        acc.x = fmaf(e1.x, g1.x, acc.x);
        acc.y = fmaf(e1.x, g1.y, acc.y);
        acc.z = fmaf(e1.x, g1.z, acc.z);
        acc.w = fmaf(e1.x, g1.w, acc.w);
    }

    // Fold the 4 edge-stream groups: lanes {q, q+8, q+16, q+24} -> lane q.
    acc.x += __shfl_xor_sync(0xffffffffu, acc.x, 8);
    acc.y += __shfl_xor_sync(0xffffffffu, acc.y, 8);
    acc.z += __shfl_xor_sync(0xffffffffu, acc.z, 8);
    acc.w += __shfl_xor_sync(0xffffffffu, acc.w, 8);
    acc.x += __shfl_xor_sync(0xffffffffu, acc.x, 16);
    acc.y += __shfl_xor_sync(0xffffffffu, acc.y, 16);
    acc.z += __shfl_xor_sync(0xffffffffu, acc.z, 16);
    acc.w += __shfl_xor_sync(0xffffffffu, acc.w, 16);

    if (lane < 6)   // lanes 0-5 cover feats 0..23 (float4 each)
        *(float4*)(dst + (size_t)w * DSTRIDE + lane * 4) = acc;
}

// ---------------------------------------------------------------------------
// kernel_launch: one build launch, then 6 SpMMs. x copied into padded bufP
// inside build; chain P->Q->P->Q->P->Q->out (final instantiation writes at
// stride 24). Default stream, no syncs, no allocations -> graph-capturable.
// ---------------------------------------------------------------------------
extern "C" void kernel_launch(void* const* d_in, const int* in_sizes, int n_in,
                              void* d_out, int out_size) {
    const float* x    = (const float*)d_in[0];  // [N_NODES, N_FEAT]
    const float* vals = (const float*)d_in[1];  // [N_EDGES]
    const void*  rraw = d_in[2];                // [N_EDGES] int32 or int64
    const void*  craw = d_in[3];                // [N_EDGES] int32 or int64
    float* out = (float*)d_out;                 // [N_NODES, N_FEAT]

    float* bufP;
    float* bufQ;
    cudaGetSymbolAddress((void**)&bufP, g_bufP);
    cudaGetSymbolAddress((void**)&bufQ, g_bufQ);

    const int sblocks = N_NODES / 8;   // 12500 blocks, warp per row

    build_csr_kernel<<<BUILD_BLOCKS, BUILD_THREADS>>>(rraw, craw, vals, x);

    // Layers 1-5 into padded buffers, final layer into d_out (stride 24).
    spmm_csr_kernel<FPAD><<<sblocks, 256>>>(bufP, bufQ);
    spmm_csr_kernel<FPAD><<<sblocks, 256>>>(bufQ, bufP);
    spmm_csr_kernel<FPAD><<<sblocks, 256>>>(bufP, bufQ);
    spmm_csr_kernel<FPAD><<<sblocks, 256>>>(bufQ, bufP);
    spmm_csr_kernel<FPAD><<<sblocks, 256>>>(bufP, bufQ);
    spmm_csr_kernel<N_FEAT><<<sblocks, 256>>>(bufQ, out);
}